// round 9
// baseline (speedup 1.0000x reference)
#include <cuda_runtime.h>
#include <cuda_fp16.h>
#include <cooperative_groups.h>

namespace cg = cooperative_groups;

#define BB 256
#define TT 2048
#define DD 40
#define HH 128
#define CC 35

// A-operand row stride (halves): 528B; 528 mod 128 = 16 -> conflict-free ldmatrix.
#define AK 264
#define KT0 11   // layer0: [x(40)->48 | h1(128)] K=176 ; pre kt 0..2, crit kt 3..10
#define KT1 16   // layer1: [h1(128) | h2(128)]   K=256 ; pre kt 0..7, crit kt 8..15

__device__ int   g_order[BB];
__device__ int   g_slen[BB];
__device__ float g_h2[BB * HH];

// ---------------- mma / ldsm / activations ----------------
__device__ __forceinline__ void mma16816(float* d, const unsigned* a, const unsigned* b) {
    asm volatile(
        "mma.sync.aligned.m16n8k16.row.col.f32.f16.f16.f32 "
        "{%0,%1,%2,%3}, {%4,%5,%6,%7}, {%8,%9}, {%0,%1,%2,%3};\n"
        : "+f"(d[0]), "+f"(d[1]), "+f"(d[2]), "+f"(d[3])
        : "r"(a[0]), "r"(a[1]), "r"(a[2]), "r"(a[3]), "r"(b[0]), "r"(b[1]));
}
__device__ __forceinline__ void ldsmx4(unsigned* a, const __half* p) {
    unsigned addr = (unsigned)__cvta_generic_to_shared(p);
    asm volatile("ldmatrix.sync.aligned.m8n8.x4.shared.b16 {%0,%1,%2,%3}, [%4];"
                 : "=r"(a[0]), "=r"(a[1]), "=r"(a[2]), "=r"(a[3])
                 : "r"(addr));
}
__device__ __forceinline__ float tanha(float x) {
    float y; asm("tanh.approx.f32 %0, %1;" : "=f"(y) : "f"(x)); return y;
}
__device__ __forceinline__ float sigf(float x) { return fmaf(0.5f, tanha(0.5f * x), 0.5f); }

// ---------------- mbarrier / st.async helpers ----------------
__device__ __forceinline__ void mbar_init(unsigned addr, unsigned cnt) {
    asm volatile("mbarrier.init.shared.b64 [%0], %1;" :: "r"(addr), "r"(cnt) : "memory");
}
__device__ __forceinline__ void mbar_expect(unsigned addr, unsigned tx) {
    asm volatile("mbarrier.arrive.expect_tx.shared.b64 _, [%0], %1;"
                 :: "r"(addr), "r"(tx) : "memory");
}
__device__ __forceinline__ void mbar_arrive_remote(unsigned local_addr, unsigned rank) {
    asm volatile("{\n\t.reg .b32 ra;\n\t"
                 "mapa.shared::cluster.u32 ra, %0, %1;\n\t"
                 "mbarrier.arrive.release.cluster.shared::cluster.b64 _, [ra];\n\t}"
                 :: "r"(local_addr), "r"(rank) : "memory");
}
__device__ __forceinline__ void mbar_wait(unsigned addr, unsigned parity) {
    asm volatile("{\n\t.reg .pred P;\n"
                 "WAIT_%=:\n\t"
                 "mbarrier.try_wait.parity.acquire.cluster.shared::cta.b64 P, [%0], %1;\n\t"
                 "@!P bra WAIT_%=;\n\t}"
                 :: "r"(addr), "r"(parity) : "memory");
}
__device__ __forceinline__ unsigned mapa_u32(unsigned addr, unsigned rank) {
    unsigned r;
    asm("mapa.shared::cluster.u32 %0, %1, %2;" : "=r"(r) : "r"(addr), "r"(rank));
    return r;
}
__device__ __forceinline__ void st_async_v4(unsigned dst, uint4 v, unsigned mbar) {
    asm volatile(
        "st.async.shared::cluster.mbarrier::complete_tx::bytes.v4.b32 [%0], {%1,%2,%3,%4}, [%5];"
        :: "r"(dst), "r"(v.x), "r"(v.y), "r"(v.z), "r"(v.w), "r"(mbar) : "memory");
}

#define CLUSTER_ARRIVE() asm volatile("barrier.cluster.arrive.aligned;" ::: "memory")
#define CLUSTER_WAIT()   asm volatile("barrier.cluster.wait.aligned;"   ::: "memory")

// ---------------- K0: rank-sort lengths (descending, stable) ----------------
__global__ void sort_kernel(const int* __restrict__ length) {
    __shared__ int len[BB];
    int i = threadIdx.x;
    len[i] = length[i];
    __syncthreads();
    int li = len[i];
    int rank = 0;
    for (int j = 0; j < BB; ++j) {
        int lj = len[j];
        rank += (lj > li) || (lj == li && j < i);
    }
    g_order[rank] = i;
    g_slen[rank]  = li;
}

// ---------------- K1: fused 2-layer LSTM, data-driven mbarrier pipeline ----------
// 16 clusters of 8 CTAs. Ranks 0-3: layer 0. Ranks 4-7: layer 1 (lag 2).
// No per-step cluster barrier: h slices move via st.async with mbarrier
// complete_tx (4KB per consumer per round); each consumer wakes on ITS data.
// 4-deep buffer ring; l1->l0 backpressure "ok" mbar waited 3 rounds late.
__global__ void __cluster_dims__(8, 1, 1) __launch_bounds__(128, 1)
lstm_fused(const float* __restrict__ x,
           const float* __restrict__ Wih0, const float* __restrict__ Whh0,
           const float* __restrict__ bih0, const float* __restrict__ bhh0,
           const float* __restrict__ Wih1, const float* __restrict__ Whh1,
           const float* __restrict__ bih1, const float* __restrict__ bhh1)
{
    cg::cluster_group cl = cg::this_cluster();
    const int rank   = (int)cl.block_rank();
    const bool is_l0 = (rank < 4);
    const int lrank  = rank & 3;
    const int group  = blockIdx.x >> 3;
    const int slotbase = group * 16;
    const int tid  = threadIdx.x;
    const int warp = tid >> 5, lane = tid & 31;

    // One buffer ring, role depends on layer:
    //   l0: cols [0,48) x | [48,176) h1-peers     l1: cols [0,128) h1 | [128,256) h2
    __shared__ __align__(16) __half Abuf[4][16][AK];
    __shared__ __align__(16) __half hstage[16][32];
    __shared__ float bsm[128];
    __shared__ int   slenS[16], morder[16];
    __shared__ __align__(8) unsigned long long mb_rx[4];    // crit operand arrivals (4096B)
    __shared__ __align__(8) unsigned long long mb_h1in[4];  // l1 only: h1 from l0 (4096B)
    __shared__ __align__(8) unsigned long long mb_ok[4];    // l0 only: 4 plain arrivals

    const float* Wih = is_l0 ? Wih0 : Wih1;
    const float* Whh = is_l0 ? Whh0 : Whh1;
    const float* bih = is_l0 ? bih0 : bih1;
    const float* bhh = is_l0 ? bhh0 : bhh1;
    const int KX  = is_l0 ? 48 : 128;
    const int DIN = is_l0 ? DD : HH;

    // ---- weights -> register fragments (4 n-tiles per warp, gate-interleaved) ----
    unsigned wf[4][16][2];
#pragma unroll
    for (int nt = 0; nt < 4; ++nt) {
        int n_local = warp * 32 + nt * 8 + (lane >> 2);
        int grow = (n_local & 3) * 128 + lrank * 32 + (n_local >> 2);
        for (int kt = 0; kt < 16; ++kt) {
            if (kt >= (is_l0 ? KT0 : KT1)) break;
#pragma unroll
            for (int f = 0; f < 2; ++f) {
                int k0 = kt * 16 + (lane & 3) * 2 + f * 8;
                int k1 = k0 + 1;
                float v0 = (k0 < KX) ? ((k0 < DIN) ? Wih[grow * DIN + k0] : 0.0f)
                                     : Whh[grow * HH + (k0 - KX)];
                float v1 = (k1 < KX) ? ((k1 < DIN) ? Wih[grow * DIN + k1] : 0.0f)
                                     : Whh[grow * HH + (k1 - KX)];
                __half2 hv = __floats2half2_rn(v0, v1);
                wf[nt][kt][f] = *reinterpret_cast<unsigned*>(&hv);
            }
        }
    }
    {
        int grow = (tid & 3) * 128 + lrank * 32 + (tid >> 2);
        bsm[tid] = bih[grow] + bhh[grow];
    }
    if (tid < 16) {
        slenS[tid]  = g_slen[slotbase + tid];
        morder[tid] = g_order[slotbase + tid];
    }
    for (int i = tid; i < 4 * 16 * AK; i += 128) ((__half*)Abuf)[i] = __float2half(0.0f);

    const unsigned rxA  = (unsigned)__cvta_generic_to_shared(&mb_rx[0]);
    const unsigned h1A  = (unsigned)__cvta_generic_to_shared(&mb_h1in[0]);
    const unsigned okA  = (unsigned)__cvta_generic_to_shared(&mb_ok[0]);
    const unsigned abA  = (unsigned)__cvta_generic_to_shared(&Abuf[0][0][0]);
    if (tid == 0) {
#pragma unroll
        for (int b = 0; b < 4; ++b) {
            mbar_init(rxA  + 8 * b, 1);
            mbar_init(h1A  + 8 * b, 1);
            mbar_init(okA  + 8 * b, 4);
            mbar_expect(rxA + 8 * b, 4096);
            mbar_expect(h1A + 8 * b, 4096);
        }
    }
    __syncthreads();
    const int maxlen = slenS[0];

    float bias0[4], bias1[4];
#pragma unroll
    for (int nt = 0; nt < 4; ++nt) {
        int c0 = warp * 32 + nt * 8 + 2 * (lane & 3);
        bias0[nt] = bsm[c0]; bias1[nt] = bsm[c0 + 1];
    }

    const int m_row = (lane >> 2) + ((lane & 1) << 3);
    const int myslen = slenS[m_row];
    const int hjb = warp * 8 + ((lane & 3) >> 1);
    float creg[4] = {0.f, 0.f, 0.f, 0.f};
    float hreg[4] = {0.f, 0.f, 0.f, 0.f};
    unsigned ph_rx = 0, ph_h1 = 0, ph_ok = 0;   // per-buffer parity bit masks

    // x prefetch: 640 elems = 5 per thread, thread-constant pointers
    const float* px[5];
    int so[5];
    if (is_l0) {
#pragma unroll
        for (int k = 0; k < 5; ++k) {
            int i = tid + k * 128;
            int m = i / DD, d = i - m * DD;
            px[k] = x + (size_t)morder[m] * TT * DD + d + DD;   // x(s+1)
            so[k] = m * AK + d;
        }
        for (int i = tid; i < 16 * DD; i += 128) {              // x(0) -> buffer 0
            int m = i / DD, d = i - m * DD;
            Abuf[0][m][d] = __float2half(x[((size_t)morder[m] * TT) * DD + d]);
        }
    }
    __syncthreads();

    const int lrowoff = (lane & 15);
    const int lcoloff = (lane >> 4) << 3;

    float acc[4][4];

    // pre-loop precompute for round 0 (l0 only: bias + x(0)-part)
    if (is_l0) {
#pragma unroll
        for (int nt = 0; nt < 4; ++nt) {
            acc[nt][0] = bias0[nt]; acc[nt][1] = bias1[nt];
            acc[nt][2] = bias0[nt]; acc[nt][3] = bias1[nt];
        }
        const __half* ar = &Abuf[0][lrowoff][lcoloff];
#pragma unroll
        for (int kt = 0; kt < 3; ++kt) {
            unsigned a[4];
            ldsmx4(a, ar + kt * 16);
            mma16816(acc[0], a, wf[0][kt]); mma16816(acc[1], a, wf[1][kt]);
            mma16816(acc[2], a, wf[2][kt]); mma16816(acc[3], a, wf[3][kt]);
        }
    }

    CLUSTER_ARRIVE(); CLUSTER_WAIT();   // mbar init + zero-init visible cluster-wide

    for (int s = 0; s <= maxlen + 1; ++s) {
        const int bC = s & 3;
        const bool compute = is_l0 ? (s < maxlen) : (s >= 2);
        const bool do_pref = is_l0 && (s + 1 < maxlen);

        float xv[5];
        if (do_pref) {
#pragma unroll
            for (int k = 0; k < 5; ++k) { xv[k] = *px[k]; px[k] += DD; }
        }

        __syncthreads();   // all sends of round s-1 done reading hstage

        // ---- wait for critical operands of buffer bC ----
        if (is_l0) {
            if (compute && s >= 1) {
                mbar_wait(rxA + 8 * bC, (ph_rx >> bC) & 1);
                ph_rx ^= 1u << bC;
                if (tid == 0) mbar_expect(rxA + 8 * bC, 4096);
            }
        } else {
            if (s >= 3 && s <= maxlen + 1) {
                mbar_wait(rxA + 8 * bC, (ph_rx >> bC) & 1);
                ph_rx ^= 1u << bC;
                if (tid == 0) mbar_expect(rxA + 8 * bC, 4096);
            }
        }

        if (compute) {
            // ---- critical (recurrent) MMA: 8 k-tiles ----
            const __half* ar = &Abuf[bC][lrowoff][lcoloff];
            if (is_l0) {
#pragma unroll
                for (int kt = 3; kt < 11; ++kt) {
                    unsigned a[4];
                    ldsmx4(a, ar + kt * 16);
                    mma16816(acc[0], a, wf[0][kt]); mma16816(acc[1], a, wf[1][kt]);
                    mma16816(acc[2], a, wf[2][kt]); mma16816(acc[3], a, wf[3][kt]);
                }
            } else {
#pragma unroll
                for (int kt = 8; kt < 16; ++kt) {
                    unsigned a[4];
                    ldsmx4(a, ar + kt * 16);
                    mma16816(acc[0], a, wf[0][kt]); mma16816(acc[1], a, wf[1][kt]);
                    mma16816(acc[2], a, wf[2][kt]); mma16816(acc[3], a, wf[3][kt]);
                }
            }
            const int t_eff = is_l0 ? s : (s - 2);
            const bool act = t_eff < myslen;
            const int sel = (lane & 1) * 2;
#pragma unroll
            for (int nt = 0; nt < 4; ++nt) {
                float o0 = __shfl_xor_sync(0xffffffffu, acc[nt][0], 1);
                float o1 = __shfl_xor_sync(0xffffffffu, acc[nt][1], 1);
                float o2 = __shfl_xor_sync(0xffffffffu, acc[nt][2], 1);
                float o3 = __shfl_xor_sync(0xffffffffu, acc[nt][3], 1);
                float iv, fv, gv, ov;
                if ((lane & 1) == 0) {
                    iv = acc[nt][sel]; fv = acc[nt][sel + 1];
                    gv = (sel == 0) ? o0 : o2; ov = (sel == 0) ? o1 : o3;
                } else {
                    iv = (sel == 0) ? o0 : o2; fv = (sel == 0) ? o1 : o3;
                    gv = acc[nt][sel]; ov = acc[nt][sel + 1];
                }
                float hn;
                if (act) {
                    float gi = sigf(iv), gf = sigf(fv), gg = tanha(gv), go = sigf(ov);
                    float cn = gf * creg[nt] + gi * gg;
                    creg[nt] = cn;
                    hn = go * tanha(cn);
                    hreg[nt] = hn;
                } else {
                    hn = hreg[nt];
                }
                hstage[m_row][hjb + nt * 2] = __float2half(hn);
            }
        }

        // deferred x(s+1) store into own buffer (s+1)&3 x-region (local only)
        if (do_pref) {
            __half* abf = (__half*)Abuf[(s + 1) & 3];
#pragma unroll
            for (int k = 0; k < 5; ++k) abf[so[k]] = __float2half(xv[k]);
        }
        __syncthreads();   // hstage ready; x stored

        // ---- sends: st.async h slice into consumers' buffers ----
        if (compute) {
            if (is_l0) {
                if (s >= 4) {   // backpressure: l1 finished pre of round s-3 (slack 2)
                    int q = (s - 3) & 3;
                    mbar_wait(okA + 8 * q, (ph_ok >> q) & 1);
                    ph_ok ^= 1u << q;
                }
                const int bA = (s + 1) & 3, bB = (s + 2) & 3;
#pragma unroll
                for (int k2 = 0; k2 < 2; ++k2) {
                    int chunk = k2 * 32 + lane, row = chunk >> 2, c4 = chunk & 3;
                    uint4 v = *reinterpret_cast<const uint4*>(&hstage[row][c4 * 8]);
                    unsigned o1 = abA + ((bA * 16 + row) * AK + 48 + lrank * 32 + c4 * 8) * 2;
                    st_async_v4(mapa_u32(o1, warp), v, mapa_u32(rxA + 8 * bA, warp));
                    unsigned o2 = abA + ((bB * 16 + row) * AK + lrank * 32 + c4 * 8) * 2;
                    st_async_v4(mapa_u32(o2, warp + 4), v, mapa_u32(h1A + 8 * bB, warp + 4));
                }
            } else {
                const int bA = (s + 1) & 3;
#pragma unroll
                for (int k2 = 0; k2 < 2; ++k2) {
                    int chunk = k2 * 32 + lane, row = chunk >> 2, c4 = chunk & 3;
                    uint4 v = *reinterpret_cast<const uint4*>(&hstage[row][c4 * 8]);
                    unsigned o1 = abA + ((bA * 16 + row) * AK + 128 + lrank * 32 + c4 * 8) * 2;
                    st_async_v4(mapa_u32(o1, warp + 4), v, mapa_u32(rxA + 8 * bA, warp + 4));
                }
            }
        }

        // l1 -> l0 ack: pre of round s-1 fully consumed (all threads past it)
        if (!is_l0 && s >= 2 && s <= maxlen + 1 && tid < 4) {
            mbar_arrive_remote(okA + 8 * ((s - 1) & 3), (unsigned)tid);
        }

        // ---- precompute next round's feed-forward MMA (off critical path) ----
        if (is_l0) {
            if (s + 1 < maxlen) {
#pragma unroll
                for (int nt = 0; nt < 4; ++nt) {
                    acc[nt][0] = bias0[nt]; acc[nt][1] = bias1[nt];
                    acc[nt][2] = bias0[nt]; acc[nt][3] = bias1[nt];
                }
                const __half* ar = &Abuf[(s + 1) & 3][lrowoff][lcoloff];
#pragma unroll
                for (int kt = 0; kt < 3; ++kt) {
                    unsigned a[4];
                    ldsmx4(a, ar + kt * 16);
                    mma16816(acc[0], a, wf[0][kt]); mma16816(acc[1], a, wf[1][kt]);
                    mma16816(acc[2], a, wf[2][kt]); mma16816(acc[3], a, wf[3][kt]);
                }
            }
        } else {
            if (s >= 1 && s <= maxlen) {
                const int bP = (s + 1) & 3;
                mbar_wait(h1A + 8 * bP, (ph_h1 >> bP) & 1);
                ph_h1 ^= 1u << bP;
                if (tid == 0) mbar_expect(h1A + 8 * bP, 4096);
#pragma unroll
                for (int nt = 0; nt < 4; ++nt) {
                    acc[nt][0] = bias0[nt]; acc[nt][1] = bias1[nt];
                    acc[nt][2] = bias0[nt]; acc[nt][3] = bias1[nt];
                }
                const __half* ar = &Abuf[bP][lrowoff][lcoloff];
#pragma unroll
                for (int kt = 0; kt < 8; ++kt) {
                    unsigned a[4];
                    ldsmx4(a, ar + kt * 16);
                    mma16816(acc[0], a, wf[0][kt]); mma16816(acc[1], a, wf[1][kt]);
                    mma16816(acc[2], a, wf[2][kt]); mma16816(acc[3], a, wf[3][kt]);
                }
            }
        }
    }

    CLUSTER_ARRIVE(); CLUSTER_WAIT();   // no CTA exits while remote ops in flight

    if (!is_l0) {
        int hb = lrank * 32;
#pragma unroll
        for (int nt = 0; nt < 4; ++nt)
            g_h2[(slotbase + m_row) * HH + hb + hjb + nt * 2] = hreg[nt];
    }
}

// ---------------- K3: LayerNorm + Linear head ----------------
__global__ void head_kernel(const float* __restrict__ lng, const float* __restrict__ lnb,
                            const float* __restrict__ fw, const float* __restrict__ fb,
                            float* __restrict__ out)
{
    int gm = blockIdx.x;
    int tid = threadIdx.x;       // 128 threads
    int bidx = g_order[gm];
    float v = g_h2[gm * HH + tid];
    float s = v, s2 = v * v;
#pragma unroll
    for (int o = 16; o; o >>= 1) {
        s  += __shfl_xor_sync(0xffffffffu, s, o);
        s2 += __shfl_xor_sync(0xffffffffu, s2, o);
    }
    __shared__ float rs[4], rs2[4], hn[HH];
    if ((tid & 31) == 0) { rs[tid >> 5] = s; rs2[tid >> 5] = s2; }
    __syncthreads();
    float mu  = (rs[0] + rs[1] + rs[2] + rs[3]) * (1.0f / HH);
    float var = (rs2[0] + rs2[1] + rs2[2] + rs2[3]) * (1.0f / HH) - mu * mu;
    hn[tid] = (v - mu) * rsqrtf(var + 1e-5f) * lng[tid] + lnb[tid];
    __syncthreads();
    if (tid < CC) {
        float acc = fb[tid];
#pragma unroll 8
        for (int j = 0; j < HH; ++j) acc += fw[tid * HH + j] * hn[j];
        out[bidx * CC + tid] = acc;
    }
}

// ---------------- launch ----------------
extern "C" void kernel_launch(void* const* d_in, const int* in_sizes, int n_in,
                              void* d_out, int out_size)
{
    (void)in_sizes; (void)n_in; (void)out_size;
    const float* x     = (const float*)d_in[0];
    const int*   len   = (const int*)  d_in[1];
    const float* Wih0  = (const float*)d_in[2];
    const float* Whh0  = (const float*)d_in[3];
    const float* bih0  = (const float*)d_in[4];
    const float* bhh0  = (const float*)d_in[5];
    const float* Wih1  = (const float*)d_in[6];
    const float* Whh1  = (const float*)d_in[7];
    const float* bih1  = (const float*)d_in[8];
    const float* bhh1  = (const float*)d_in[9];
    const float* lng   = (const float*)d_in[10];
    const float* lnb   = (const float*)d_in[11];
    const float* fcw   = (const float*)d_in[12];
    const float* fcb   = (const float*)d_in[13];
    float* out = (float*)d_out;

    sort_kernel<<<1, BB>>>(len);
    lstm_fused<<<128, 128>>>(x, Wih0, Whh0, bih0, bhh0, Wih1, Whh1, bih1, bhh1);
    head_kernel<<<BB, 128>>>(lng, lnb, fcw, fcb, out);
}

// round 11
// speedup vs baseline: 1.2467x; 1.2467x over previous
#include <cuda_runtime.h>
#include <cuda_fp16.h>
#include <cooperative_groups.h>

namespace cg = cooperative_groups;

#define BB 256
#define TT 2048
#define DD 40
#define HH 128
#define CC 35

// A-operand row stride (halves): 528B; 528 mod 128 = 16 -> conflict-free ldmatrix.
#define AK 264
#define KT0 11   // layer0: [x(40)->48 | h1(128)] K=176 ; pre kt 0..2, crit kt 3..10
#define KT1 16   // layer1: [h1(128) | h2(128)]   K=256 ; pre kt 0..7, crit kt 8..15

__device__ int   g_order[BB];
__device__ int   g_slen[BB];
__device__ float g_h2[BB * HH];

// ---------------- mma / ldsm / activations ----------------
__device__ __forceinline__ void mma16816(float* d, const unsigned* a, const unsigned* b) {
    asm volatile(
        "mma.sync.aligned.m16n8k16.row.col.f32.f16.f16.f32 "
        "{%0,%1,%2,%3}, {%4,%5,%6,%7}, {%8,%9}, {%0,%1,%2,%3};\n"
        : "+f"(d[0]), "+f"(d[1]), "+f"(d[2]), "+f"(d[3])
        : "r"(a[0]), "r"(a[1]), "r"(a[2]), "r"(a[3]), "r"(b[0]), "r"(b[1]));
}
__device__ __forceinline__ void ldsmx4(unsigned* a, const __half* p) {
    unsigned addr = (unsigned)__cvta_generic_to_shared(p);
    asm volatile("ldmatrix.sync.aligned.m8n8.x4.shared.b16 {%0,%1,%2,%3}, [%4];"
                 : "=r"(a[0]), "=r"(a[1]), "=r"(a[2]), "=r"(a[3])
                 : "r"(addr));
}
__device__ __forceinline__ float tanha(float x) {
    float y; asm("tanh.approx.f32 %0, %1;" : "=f"(y) : "f"(x)); return y;
}
__device__ __forceinline__ float sigf(float x) { return fmaf(0.5f, tanha(0.5f * x), 0.5f); }

#define CLUSTER_ARRIVE() asm volatile("barrier.cluster.arrive.aligned;" ::: "memory")
#define CLUSTER_WAIT()   asm volatile("barrier.cluster.wait.aligned;"   ::: "memory")

// ---------------- K0: rank-sort lengths (descending, stable) ----------------
__global__ void sort_kernel(const int* __restrict__ length) {
    __shared__ int len[BB];
    int i = threadIdx.x;
    len[i] = length[i];
    __syncthreads();
    int li = len[i];
    int rank = 0;
    for (int j = 0; j < BB; ++j) {
        int lj = len[j];
        rank += (lj > li) || (lj == li && j < i);
    }
    g_order[rank] = i;
    g_slen[rank]  = li;
}

// ---------------- K1: fused 2-layer LSTM ----------------
// 16 clusters of 8 CTAs. Ranks 0-3: layer 0 (lag 0). Ranks 4-7: layer 1 (lag 2).
// Each CTA: M=16 rows, N=128 gate cols, 128 thr = 4 warps x 4 n-tiles.
// Column map: n-tile nt == GATE, tile covers h-indices [warp*8, warp*8+8).
// => each thread's 4 accumulators (per cell) hold all four gates of one
// (row, h) cell: NO shuffles in the epilogue.
// Feed-forward K-half precomputed after the arrive (off recurrence path).
__global__ void __cluster_dims__(8, 1, 1) __launch_bounds__(128, 1)
lstm_fused(const float* __restrict__ x,
           const float* __restrict__ Wih0, const float* __restrict__ Whh0,
           const float* __restrict__ bih0, const float* __restrict__ bhh0,
           const float* __restrict__ Wih1, const float* __restrict__ Whh1,
           const float* __restrict__ bih1, const float* __restrict__ bhh1)
{
    cg::cluster_group cl = cg::this_cluster();
    const int rank   = (int)cl.block_rank();
    const bool is_l0 = (rank < 4);
    const int lrank  = rank & 3;
    const int group  = blockIdx.x >> 3;
    const int slotbase = group * 16;
    const int tid  = threadIdx.x;
    const int warp = tid >> 5, lane = tid & 31;

    __shared__ __align__(16) __half A0[2][16][AK];   // layer-0 CTAs
    __shared__ __align__(16) __half A1[3][16][AK];   // layer-1 CTAs
    __shared__ __align__(16) __half hstage[16][40];  // 80B row stride: conflict-free
    __shared__ int slenS[16], morder[16];

    const float* Wih = is_l0 ? Wih0 : Wih1;
    const float* Whh = is_l0 ? Whh0 : Whh1;
    const float* bih = is_l0 ? bih0 : bih1;
    const float* bhh = is_l0 ? bhh0 : bhh1;
    const int KX  = is_l0 ? 48 : 128;
    const int DIN = is_l0 ? DD : HH;

    // ---- weights -> register fragments (nt == gate) ----
    unsigned wf[4][16][2];
#pragma unroll
    for (int nt = 0; nt < 4; ++nt) {
        int grow = nt * 128 + lrank * 32 + warp * 8 + (lane >> 2);
        for (int kt = 0; kt < 16; ++kt) {
            if (kt >= (is_l0 ? KT0 : KT1)) break;
#pragma unroll
            for (int f = 0; f < 2; ++f) {
                int k0 = kt * 16 + (lane & 3) * 2 + f * 8;
                int k1 = k0 + 1;
                float v0 = (k0 < KX) ? ((k0 < DIN) ? Wih[grow * DIN + k0] : 0.0f)
                                     : Whh[grow * HH + (k0 - KX)];
                float v1 = (k1 < KX) ? ((k1 < DIN) ? Wih[grow * DIN + k1] : 0.0f)
                                     : Whh[grow * HH + (k1 - KX)];
                __half2 hv = __floats2half2_rn(v0, v1);
                wf[nt][kt][f] = *reinterpret_cast<unsigned*>(&hv);
            }
        }
    }
    // ---- bias -> registers (acc col = gate nt, h = warp*8 + 2*(lane&3)+{0,1}) ----
    float bias0[4], bias1[4];
#pragma unroll
    for (int nt = 0; nt < 4; ++nt) {
        int g = nt * 128 + lrank * 32 + warp * 8 + 2 * (lane & 3);
        bias0[nt] = bih[g] + bhh[g];
        bias1[nt] = bih[g + 1] + bhh[g + 1];
    }
    if (tid < 16) {
        slenS[tid]  = g_slen[slotbase + tid];
        morder[tid] = g_order[slotbase + tid];
    }
    for (int i = tid; i < 2 * 16 * AK; i += 128) ((__half*)A0)[i] = __float2half(0.0f);
    for (int i = tid; i < 3 * 16 * AK; i += 128) ((__half*)A1)[i] = __float2half(0.0f);
    __syncthreads();
    const int maxlen = slenS[0];

    // per-thread cell ownership: rows r0, r0+8; h-cols hj, hj+1 (one half2 pair)
    const int r0  = lane >> 2;
    const int hj  = warp * 8 + 2 * (lane & 3);
    const int slen_a = slenS[r0], slen_b = slenS[r0 + 8];
    float creg[4] = {0.f, 0.f, 0.f, 0.f};   // q: (r0,hj),(r0,hj+1),(r0+8,hj),(r0+8,hj+1)
    float hreg[4] = {0.f, 0.f, 0.f, 0.f};

    // x prefetch: 640 elems = 5 per thread; loaded TWO steps ahead (xvC/xvN)
    const float* px[5];
    int so[5];
    float xvC[5], xvN[5];
    if (is_l0) {
#pragma unroll
        for (int k = 0; k < 5; ++k) {
            int i = tid + k * 128;
            int m = i / DD, d = i - m * DD;
            px[k] = x + (size_t)morder[m] * TT * DD + d;
            so[k] = m * AK + d;
        }
        for (int i = tid; i < 16 * DD; i += 128) {   // x(0) -> buffer 0
            int m = i / DD, d = i - m * DD;
            A0[0][m][d] = __float2half(x[((size_t)morder[m] * TT) * DD + d]);
        }
        if (maxlen > 1) {                            // xvC = x(1)
#pragma unroll
            for (int k = 0; k < 5; ++k) xvC[k] = px[k][DD];
        }
#pragma unroll
        for (int k = 0; k < 5; ++k) px[k] += 2 * DD; // px -> x(2)
    }
    __syncthreads();

    const int lrowoff = (lane & 15);
    const int lcoloff = (lane >> 4) << 3;

    float acc[4][4];

    // pre-loop precompute for round 0 (l0 only: bias + x(0)-part)
    if (is_l0) {
#pragma unroll
        for (int nt = 0; nt < 4; ++nt) {
            acc[nt][0] = bias0[nt]; acc[nt][1] = bias1[nt];
            acc[nt][2] = bias0[nt]; acc[nt][3] = bias1[nt];
        }
        const __half* ar = &A0[0][lrowoff][lcoloff];
#pragma unroll
        for (int kt = 0; kt < 3; ++kt) {
            unsigned a[4];
            ldsmx4(a, ar + kt * 16);
            mma16816(acc[0], a, wf[0][kt]); mma16816(acc[1], a, wf[1][kt]);
            mma16816(acc[2], a, wf[2][kt]); mma16816(acc[3], a, wf[3][kt]);
        }
    }

    CLUSTER_ARRIVE();   // zero-init + buffer0 published

    for (int s = 0; s <= maxlen + 1; ++s) {
        const int p2 = s & 1;
        const int b3 = s % 3;
        const bool compute = is_l0 ? (s < maxlen) : (s >= 2);

        // issue x(s+2) loads before the barrier wait (2-step latency slack)
        if (is_l0 && s + 2 < maxlen) {
#pragma unroll
            for (int k = 0; k < 5; ++k) { xvN[k] = *px[k]; px[k] += DD; }
        }

        CLUSTER_WAIT();   // recurrent operands for this round have landed

        if (compute) {
            // ---- critical (recurrent) MMA: 8 k-tiles ----
            if (is_l0) {
                const __half* ar = &A0[p2][lrowoff][lcoloff];
#pragma unroll
                for (int kt = 3; kt < 11; ++kt) {
                    unsigned a[4];
                    ldsmx4(a, ar + kt * 16);
                    mma16816(acc[0], a, wf[0][kt]); mma16816(acc[1], a, wf[1][kt]);
                    mma16816(acc[2], a, wf[2][kt]); mma16816(acc[3], a, wf[3][kt]);
                }
            } else {
                const __half* ar = &A1[b3][lrowoff][lcoloff];
#pragma unroll
                for (int kt = 8; kt < 16; ++kt) {
                    unsigned a[4];
                    ldsmx4(a, ar + kt * 16);
                    mma16816(acc[0], a, wf[0][kt]); mma16816(acc[1], a, wf[1][kt]);
                    mma16816(acc[2], a, wf[2][kt]); mma16816(acc[3], a, wf[3][kt]);
                }
            }
            // ---- shuffle-free epilogue: all 4 gates of each cell in-thread ----
            const int t_eff = is_l0 ? s : (s - 2);
#pragma unroll
            for (int q = 0; q < 4; ++q) {
                const bool act = t_eff < ((q < 2) ? slen_a : slen_b);
                float hn;
                if (act) {
                    float gi = sigf(acc[0][q]);
                    float gf = sigf(acc[1][q]);
                    float gg = tanha(acc[2][q]);
                    float go = sigf(acc[3][q]);
                    float cn = gf * creg[q] + gi * gg;
                    creg[q] = cn;
                    hn = go * tanha(cn);
                    hreg[q] = hn;
                } else {
                    hn = hreg[q];
                }
                hreg[q] = hreg[q];  // keep
                ((void)hn);
            }
            *reinterpret_cast<__half2*>(&hstage[r0][hj])     = __floats2half2_rn(hreg[0], hreg[1]);
            *reinterpret_cast<__half2*>(&hstage[r0 + 8][hj]) = __floats2half2_rn(hreg[2], hreg[3]);
        }

        // deferred x(s+1) store into own buffer (s+1)&1 x-region (local only)
        if (is_l0 && s + 1 < maxlen) {
            __half* abf = (__half*)A0[p2 ^ 1];
#pragma unroll
            for (int k = 0; k < 5; ++k) abf[so[k]] = __float2half(xvC[k]);
#pragma unroll
            for (int k = 0; k < 5; ++k) xvC[k] = xvN[k];
        }
        __syncthreads();   // hstage complete; this buffer's reads complete

        // ---- DSMEM broadcast of h slice (warp w -> rank w / w+4) ----
        if (compute) {
            const int bn2 = (s + 1) & 1;          // l0-consumer buffer
            const int bh1 = (s + 2) % 3;          // l1-consumer h1 buffer (from l0)
            const int bh2 = (s + 1) % 3;          // l1-consumer h2 buffer (from l1)
#pragma unroll
            for (int k2 = 0; k2 < 2; ++k2) {
                int chunk = k2 * 32 + lane;
                int row = chunk >> 2, c4 = chunk & 3;
                uint4 v = *reinterpret_cast<const uint4*>(&hstage[row][c4 * 8]);
                if (is_l0) {
                    uint4* d0 = (uint4*)cl.map_shared_rank(
                        (void*)&A0[bn2][row][48 + lrank * 32 + c4 * 8], warp);
                    *d0 = v;
                    uint4* d1 = (uint4*)cl.map_shared_rank(
                        (void*)&A1[bh1][row][lrank * 32 + c4 * 8], warp + 4);
                    *d1 = v;
                } else {
                    uint4* d1 = (uint4*)cl.map_shared_rank(
                        (void*)&A1[bh2][row][128 + lrank * 32 + c4 * 8], warp + 4);
                    *d1 = v;
                }
            }
        }
        CLUSTER_ARRIVE();   // release: h writes ordered before consumers' wait

        // ---- precompute next round's feed-forward MMA (off critical path) ----
        if (is_l0) {
            if (s + 1 < maxlen) {
#pragma unroll
                for (int nt = 0; nt < 4; ++nt) {
                    acc[nt][0] = bias0[nt]; acc[nt][1] = bias1[nt];
                    acc[nt][2] = bias0[nt]; acc[nt][3] = bias1[nt];
                }
                const __half* ar = &A0[p2 ^ 1][lrowoff][lcoloff];
#pragma unroll
                for (int kt = 0; kt < 3; ++kt) {
                    unsigned a[4];
                    ldsmx4(a, ar + kt * 16);
                    mma16816(acc[0], a, wf[0][kt]); mma16816(acc[1], a, wf[1][kt]);
                    mma16816(acc[2], a, wf[2][kt]); mma16816(acc[3], a, wf[3][kt]);
                }
            }
        } else {
            if (s + 1 >= 2 && s <= maxlen) {
#pragma unroll
                for (int nt = 0; nt < 4; ++nt) {
                    acc[nt][0] = bias0[nt]; acc[nt][1] = bias1[nt];
                    acc[nt][2] = bias0[nt]; acc[nt][3] = bias1[nt];
                }
                const __half* ar = &A1[(s + 1) % 3][lrowoff][lcoloff];
#pragma unroll
                for (int kt = 0; kt < 8; ++kt) {
                    unsigned a[4];
                    ldsmx4(a, ar + kt * 16);
                    mma16816(acc[0], a, wf[0][kt]); mma16816(acc[1], a, wf[1][kt]);
                    mma16816(acc[2], a, wf[2][kt]); mma16816(acc[3], a, wf[3][kt]);
                }
            }
        }
    }

    CLUSTER_WAIT();   // pair final arrive; peers done writing into my smem

    if (!is_l0) {
        int hb = lrank * 32 + hj;
        g_h2[(slotbase + r0) * HH + hb]         = hreg[0];
        g_h2[(slotbase + r0) * HH + hb + 1]     = hreg[1];
        g_h2[(slotbase + r0 + 8) * HH + hb]     = hreg[2];
        g_h2[(slotbase + r0 + 8) * HH + hb + 1] = hreg[3];
    }
}

// ---------------- K3: LayerNorm + Linear head ----------------
__global__ void head_kernel(const float* __restrict__ lng, const float* __restrict__ lnb,
                            const float* __restrict__ fw, const float* __restrict__ fb,
                            float* __restrict__ out)
{
    int gm = blockIdx.x;
    int tid = threadIdx.x;       // 128 threads
    int bidx = g_order[gm];
    float v = g_h2[gm * HH + tid];
    float s = v, s2 = v * v;
#pragma unroll
    for (int o = 16; o; o >>= 1) {
        s  += __shfl_xor_sync(0xffffffffu, s, o);
        s2 += __shfl_xor_sync(0xffffffffu, s2, o);
    }
    __shared__ float rs[4], rs2[4], hn[HH];
    if ((tid & 31) == 0) { rs[tid >> 5] = s; rs2[tid >> 5] = s2; }
    __syncthreads();
    float mu  = (rs[0] + rs[1] + rs[2] + rs[3]) * (1.0f / HH);
    float var = (rs2[0] + rs2[1] + rs2[2] + rs2[3]) * (1.0f / HH) - mu * mu;
    hn[tid] = (v - mu) * rsqrtf(var + 1e-5f) * lng[tid] + lnb[tid];
    __syncthreads();
    if (tid < CC) {
        float acc = fb[tid];
#pragma unroll 8
        for (int j = 0; j < HH; ++j) acc += fw[tid * HH + j] * hn[j];
        out[bidx * CC + tid] = acc;
    }
}

// ---------------- launch ----------------
extern "C" void kernel_launch(void* const* d_in, const int* in_sizes, int n_in,
                              void* d_out, int out_size)
{
    (void)in_sizes; (void)n_in; (void)out_size;
    const float* x     = (const float*)d_in[0];
    const int*   len   = (const int*)  d_in[1];
    const float* Wih0  = (const float*)d_in[2];
    const float* Whh0  = (const float*)d_in[3];
    const float* bih0  = (const float*)d_in[4];
    const float* bhh0  = (const float*)d_in[5];
    const float* Wih1  = (const float*)d_in[6];
    const float* Whh1  = (const float*)d_in[7];
    const float* bih1  = (const float*)d_in[8];
    const float* bhh1  = (const float*)d_in[9];
    const float* lng   = (const float*)d_in[10];
    const float* lnb   = (const float*)d_in[11];
    const float* fcw   = (const float*)d_in[12];
    const float* fcb   = (const float*)d_in[13];
    float* out = (float*)d_out;

    sort_kernel<<<1, BB>>>(len);
    lstm_fused<<<128, 128>>>(x, Wih0, Whh0, bih0, bhh0, Wih1, Whh1, bih1, bhh1);
    head_kernel<<<BB, 128>>>(lng, lnb, fcw, fcb, out);
}